// round 5
// baseline (speedup 1.0000x reference)
#include <cuda_runtime.h>
#include <math.h>

#define HH 512
#define NN 64
#define LL 4096
#define MM 2048
#define LF 2049
#define NBLK 592          // Cauchy grid: 4 blocks/SM on 148 SMs, robust on 152
#define NITEM 4096        // 512 heads x 8 segments (256 bins each)

typedef unsigned long long ull;

__device__ float2 g_X[HH * LF];   // Cauchy spectrum X[h][l], l=0..2048
__device__ float2 g_tw[1025];     // exp(+i*pi*j/2048), j=0..1024

__device__ __forceinline__ ull f2_fma(ull a, ull b, ull c) {
    ull d; asm("fma.rn.f32x2 %0, %1, %2, %3;" : "=l"(d) : "l"(a), "l"(b), "l"(c)); return d;
}
__device__ __forceinline__ ull f2_mul(ull a, ull b) {
    ull d; asm("mul.rn.f32x2 %0, %1, %2;" : "=l"(d) : "l"(a), "l"(b)); return d;
}
__device__ __forceinline__ ull f2_add(ull a, ull b) {
    ull d; asm("add.rn.f32x2 %0, %1, %2;" : "=l"(d) : "l"(a), "l"(b)); return d;
}
__device__ __forceinline__ ull f2_pack(float lo, float hi) {
    ull d; asm("mov.b64 %0, {%1, %2};" : "=l"(d) : "f"(lo), "f"(hi)); return d;
}
__device__ __forceinline__ float2 f2_unpack(ull a) {
    float lo, hi; asm("mov.b64 {%0, %1}, %2;" : "=f"(lo), "=f"(hi) : "l"(a));
    return make_float2(lo, hi);
}
__device__ __forceinline__ float frcp(float x) {
    float r; asm("rcp.approx.f32 %0, %1;" : "=f"(r) : "f"(x)); return r;
}

// ============================================================================
// Kernel A: Cauchy sums. Grid NBLK x 128 threads. Block b owns contiguous
// items [b*NITEM/NBLK, (b+1)*NITEM/NBLK); item = (h, seg): 256 bins
// l = seg*256 + [0,256), 2 bins/thread. Owner of seg 7 also does l=2048.
// ============================================================================
__global__ __launch_bounds__(128) void s4_cauchy(
    const float* __restrict__ A_real,
    const float* __restrict__ A_imag,
    const float* __restrict__ Bm,
    const float* __restrict__ Cm,
    const float* __restrict__ Pm,
    const float* __restrict__ inv_dt)
{
    __shared__ ulonglong2 s_coef[NN / 2][9];

    const int tid = threadIdx.x;
    const int b   = blockIdx.x;

    // publish twiddle table (blocks 0..8 cover j=0..1024+)
    if (b < 9) {
        const int j = b * 128 + tid;
        if (j <= 1024) {
            float s, c;
            sincosf((float)j * (3.14159265358979323846f / 2048.0f), &s, &c);
            g_tw[j] = make_float2(c, s);
        }
    }

    const int item_lo = (b * NITEM) / NBLK;
    const int item_hi = ((b + 1) * NITEM) / NBLK;
    const float ANG = 3.14159265358979323846f / 4096.0f;

    int cur_h = -1;
    for (int it = item_lo; it < item_hi; it++) {
        const int h   = it >> 3;
        const int seg = it & 7;

        if (h != cur_h) {
            __syncthreads();                  // previous item done with s_coef
            if (tid < NN) {
                const int n  = tid;
                const float dt = expf(inv_dt[h]);
                const float ar = -expf(A_real[h * NN + n]) * dt;
                const float ai =  A_imag[h * NN + n] * dt;

                const int base = (h * NN + n) * 2;
                const float bx = Bm[base], by = Bm[base + 1];
                const float cx = Cm[base], cy = Cm[base + 1];
                const float px = Pm[base], py = Pm[base + 1];

                float vr[4], vi[4];
                vr[0] = (bx * cx - by * cy) * dt;  vi[0] = (bx * cy + by * cx) * dt;
                vr[1] = (bx * px + by * py) * dt;  vi[1] = (by * px - bx * py) * dt;
                vr[2] = (px * cx - py * cy) * dt;  vi[2] = (px * cy + py * cx) * dt;
                vr[3] = (px * px + py * py) * dt;  vi[3] = 0.0f;

                float* c = (float*)&s_coef[n >> 1][0];
                const int o = n & 1;
                const float ccoef = -2.0f * ar;
                c[0 + o] = ar * ar + ai * ai;              // m
                c[2 + o] = ccoef * ccoef;                  // c^2
                #pragma unroll
                for (int ab = 0; ab < 4; ab++) {
                    const float p = -2.0f * (vr[ab] * ar + vi[ab] * ai);
                    const float q =  2.0f * vr[ab];
                    const int bo = 4 + ab * 8;
                    c[bo + 0 + o] = p;
                    c[bo + 2 + o] = q * ccoef;             // qc
                    c[bo + 4 + o] = q;
                    c[bo + 6 + o] = -p * ccoef;            // npc
                }
            }
            __syncthreads();
            cur_h = h;
        }

        const int l0 = seg * 256 + tid;       // bins l0, l0+128
        float yv[2];
        ull y2v[2], ny2v[2];
        #pragma unroll
        for (int q = 0; q < 2; q++) {
            const float y = 2.0f * tanf((float)(l0 + q * 128) * ANG);
            yv[q] = y;
            y2v[q]  = f2_pack(y * y, y * y);
            ny2v[q] = y2v[q] ^ 0x8000000080000000ULL;
        }

        ull accr[2][4], acci[2][4];
        #pragma unroll
        for (int q = 0; q < 2; q++)
            #pragma unroll
            for (int ab = 0; ab < 4; ab++) { accr[q][ab] = 0; acci[q][ab] = 0; }

        #pragma unroll 4
        for (int k = 0; k < NN / 2; k++) {
            const ulonglong2* cc = &s_coef[k][0];
            const ulonglong2 c0 = cc[0];

            ull dinv[2], y2inv[2], invv[2];
            #pragma unroll
            for (int q = 0; q < 2; q++) {
                const ull dr  = f2_add(c0.x, ny2v[q]);
                const ull mag = f2_fma(dr, dr, f2_mul(c0.y, y2v[q]));
                const float2 m = f2_unpack(mag);
                const ull inv = f2_pack(frcp(m.x), frcp(m.y));
                invv[q]  = inv;
                dinv[q]  = f2_mul(dr, inv);
                y2inv[q] = f2_mul(y2v[q], inv);
            }

            #pragma unroll
            for (int ab = 0; ab < 4; ab++) {
                const ulonglong2 ca = cc[1 + 2 * ab];      // (p, qc)
                const ulonglong2 cb = cc[2 + 2 * ab];      // (q, npc)
                #pragma unroll
                for (int q = 0; q < 2; q++) {
                    accr[q][ab] = f2_fma(ca.x, dinv[q], f2_fma(ca.y, y2inv[q], accr[q][ab]));
                    acci[q][ab] = f2_fma(cb.x, dinv[q], f2_fma(cb.y, invv[q],  acci[q][ab]));
                }
            }
        }

        #pragma unroll
        for (int q = 0; q < 2; q++) {
            const float y = yv[q];
            const int   l = l0 + q * 128;
            const float2 sr0 = f2_unpack(accr[q][0]), si0 = f2_unpack(acci[q][0]);
            const float2 sr1 = f2_unpack(accr[q][1]), si1 = f2_unpack(acci[q][1]);
            const float2 sr2 = f2_unpack(accr[q][2]), si2 = f2_unpack(acci[q][2]);
            const float2 sr3 = f2_unpack(accr[q][3]), si3 = f2_unpack(acci[q][3]);
            const float r00r = sr0.x + sr0.y, r00i = (si0.x + si0.y) * y;
            const float r01r = sr1.x + sr1.y, r01i = (si1.x + si1.y) * y;
            const float r10r = sr2.x + sr2.y, r10i = (si2.x + si2.y) * y;
            const float r11r = sr3.x + sr3.y, r11i = (si3.x + si3.y) * y;

            const float cr = 1.0f + r11r, ci = r11i;
            const float cinv = frcp(cr * cr + ci * ci);
            const float trm = r01r * r10r - r01i * r10i;
            const float tim = r01r * r10i + r01i * r10r;
            const float qr = (trm * cr + tim * ci) * cinv;
            const float qi = (tim * cr - trm * ci) * cinv;
            const float kr = r00r - qr;
            const float ki = r00i - qi;
            const float hy = 0.5f * y;
            float fr = kr - ki * hy;
            float fi = ki + kr * hy;
            if (l == 0) fi = 0.0f;
            g_X[h * LF + l] = make_float2(fr, fi);
        }

        // Nyquist bin l=2048 (scalar), owned by (h, seg 7)
        if (seg == 7 && tid == 0) {
            const float y  = 2.0f * tanf(2048.0f * ANG);
            const float y2 = y * y;
            float rr[4] = {0, 0, 0, 0}, riy[4] = {0, 0, 0, 0};
            for (int n = 0; n < NN; n++) {
                const float* c = (const float*)&s_coef[n >> 1][0];
                const int o = n & 1;
                const float dr = c[0 + o] - y2;
                const float inv = frcp(dr * dr + c[2 + o] * y2);
                const float dinv = dr * inv;
                const float y2inv = y2 * inv;
                #pragma unroll
                for (int ab = 0; ab < 4; ab++) {
                    const int bo = 4 + ab * 8;
                    rr[ab]  += c[bo + 0 + o] * dinv + c[bo + 2 + o] * y2inv;
                    riy[ab] += c[bo + 4 + o] * dinv + c[bo + 6 + o] * inv;
                }
            }
            const float r00r = rr[0];
            const float r01r = rr[1], r01i = riy[1] * y;
            const float r10r = rr[2], r10i = riy[2] * y;
            const float r11r = rr[3], r11i = riy[3] * y;
            const float cr = 1.0f + r11r, ci = r11i;
            const float cinv = frcp(cr * cr + ci * ci);
            const float trm = r01r * r10r - r01i * r10i;
            const float tim = r01r * r10i + r01i * r10r;
            const float qr = (trm * cr + tim * ci) * cinv;
            const float qi = (tim * cr - trm * ci) * cinv;
            const float kr = r00r - qr;
            const float ki = riy[0] * y - qi;
            const float fr = kr - ki * (0.5f * y);
            g_X[h * LF + 2048] = make_float2(fr, 0.0f);
        }
    }
}

// ============================================================================
// Kernel B: packed real inverse FFT (irfft-4096 via complex iFFT-2048),
// padded smem, one sync per pass. grid HH, block 512.
// ============================================================================
#define IDX(i) ((i) + ((i) >> 5))

__global__ __launch_bounds__(512) void s4_fft(float* __restrict__ out)
{
    __shared__ float2 spec[MM + MM / 32];
    __shared__ float2 tw[1025];

    const int h   = blockIdx.x;
    const int tid = threadIdx.x;

    for (int j = tid; j <= 1024; j += 512) tw[j] = g_tw[j];
    __syncthreads();

    // build Z, store bit-reversed
    const float2* Xh = &g_X[h * LF];
    for (int k = tid; k < MM; k += 512) {
        const float2 Xk = Xh[k];
        const float2 Xm = Xh[MM - k];
        float2 w;
        if (k <= 1024) w = tw[k];
        else { const float2 t = tw[k - 1024]; w = make_float2(-t.y, t.x); }
        const float arr = Xk.x + Xm.x, aii = Xk.y - Xm.y;
        const float brr = Xk.x - Xm.x, bii = Xk.y + Xm.y;
        const float zr = arr - (w.x * bii + w.y * brr);
        const float zi = aii + (w.x * brr - w.y * bii);
        spec[IDX(__brev(k) >> 21)] = make_float2(zr, zi);
    }
    __syncthreads();

    // fused radix-4 DIT passes; per-thread read/write sets coincide, so only
    // one barrier per pass is required.
    #pragma unroll
    for (int s = 1; s <= 9; s += 2) {
        const int hh = 1 << (s - 1);
        const int j  = tid & (hh - 1);
        const int bb = ((tid >> (s - 1)) << (s + 1)) + j;
        const int i0 = IDX(bb), i1 = IDX(bb + hh), i2 = IDX(bb + 2 * hh), i3 = IDX(bb + 3 * hh);

        const float2 w2 = tw[j << (11 - s)];
        const float w1x = w2.x * w2.x - w2.y * w2.y;
        const float w1y = 2.0f * w2.x * w2.y;

        const float2 x0 = spec[i0], x1 = spec[i1], x2 = spec[i2], x3 = spec[i3];

        const float t1x = w1x * x1.x - w1y * x1.y, t1y = w1x * x1.y + w1y * x1.x;
        const float a0x = x0.x + t1x, a0y = x0.y + t1y;
        const float a1x = x0.x - t1x, a1y = x0.y - t1y;
        const float t3x = w1x * x3.x - w1y * x3.y, t3y = w1x * x3.y + w1y * x3.x;
        const float a2x = x2.x + t3x, a2y = x2.y + t3y;
        const float a3x = x2.x - t3x, a3y = x2.y - t3y;

        const float t2x = w2.x * a2x - w2.y * a2y, t2y = w2.x * a2y + w2.y * a2x;
        const float c3x = w2.x * a3x - w2.y * a3y, c3y = w2.x * a3y + w2.y * a3x;

        spec[i0] = make_float2(a0x + t2x, a0y + t2y);
        spec[i2] = make_float2(a0x - t2x, a0y - t2y);
        spec[i1] = make_float2(a1x - c3y, a1y + c3x);
        spec[i3] = make_float2(a1x + c3y, a1y - c3x);
        __syncthreads();
    }

    // final radix-2 stage
    for (int j = tid; j < 1024; j += 512) {
        float2 w;
        const int t = 2 * j;
        if (t <= 1024) w = tw[t];
        else { const float2 u = tw[t - 1024]; w = make_float2(-u.y, u.x); }
        const float2 a = spec[IDX(j)];
        const float2 b = spec[IDX(j + 1024)];
        const float trr = w.x * b.x - w.y * b.y;
        const float tii = w.x * b.y + w.y * b.x;
        spec[IDX(j)]        = make_float2(a.x + trr, a.y + tii);
        spec[IDX(j + 1024)] = make_float2(a.x - trr, a.y - tii);
    }
    __syncthreads();

    float2* out2 = (float2*)(out + h * LL);
    const float scale = 1.0f / (float)LL;
    for (int n = tid; n < MM; n += 512) {
        const float2 z = spec[IDX(n)];
        out2[n] = make_float2(z.x * scale, z.y * scale);
    }
}

extern "C" void kernel_launch(void* const* d_in, const int* in_sizes, int n_in,
                              void* d_out, int out_size)
{
    (void)in_sizes; (void)n_in; (void)out_size;
    s4_cauchy<<<NBLK, 128>>>(
        (const float*)d_in[0],   // A_real (H, N)
        (const float*)d_in[1],   // A_imag (H, N)
        (const float*)d_in[2],   // B (1, H, N, 2)
        (const float*)d_in[3],   // C (1, H, N, 2)
        (const float*)d_in[4],   // P (1, H, N, 2)
        (const float*)d_in[5]);  // inv_dt (H,)
    s4_fft<<<HH, 512>>>((float*)d_out);
}

// round 7
// speedup vs baseline: 1.1231x; 1.1231x over previous
#include <cuda_runtime.h>
#include <math.h>

#define HH 512
#define NN 64
#define LL 4096
#define MM 2048
#define LF 2049

typedef unsigned long long ull;

__device__ float2 g_X[HH * LF];   // Cauchy spectrum X[h][l], l=0..2048
__device__ float2 g_tw[1025];     // exp(+i*pi*j/2048), j=0..1024

__device__ __forceinline__ ull f2_fma(ull a, ull b, ull c) {
    ull d; asm("fma.rn.f32x2 %0, %1, %2, %3;" : "=l"(d) : "l"(a), "l"(b), "l"(c)); return d;
}
__device__ __forceinline__ ull f2_mul(ull a, ull b) {
    ull d; asm("mul.rn.f32x2 %0, %1, %2;" : "=l"(d) : "l"(a), "l"(b)); return d;
}
__device__ __forceinline__ ull f2_add(ull a, ull b) {
    ull d; asm("add.rn.f32x2 %0, %1, %2;" : "=l"(d) : "l"(a), "l"(b)); return d;
}
__device__ __forceinline__ ull f2_pack(float lo, float hi) {
    ull d; asm("mov.b64 %0, {%1, %2};" : "=l"(d) : "f"(lo), "f"(hi)); return d;
}
__device__ __forceinline__ float2 f2_unpack(ull a) {
    float lo, hi; asm("mov.b64 {%0, %1}, %2;" : "=f"(lo), "=f"(hi) : "l"(a));
    return make_float2(lo, hi);
}
__device__ __forceinline__ float frcp(float x) {
    float r; asm("rcp.approx.f32 %0, %1;" : "=f"(r) : "f"(x)); return r;
}

// complex helpers
__device__ __forceinline__ float2 cmul(float2 a, float2 b) {
    return make_float2(a.x * b.x - a.y * b.y, a.x * b.y + a.y * b.x);
}
__device__ __forceinline__ float2 csq(float2 a) {
    return make_float2(a.x * a.x - a.y * a.y, 2.0f * a.x * a.y);
}
__device__ __forceinline__ float2 cadd(float2 a, float2 b) { return make_float2(a.x + b.x, a.y + b.y); }
__device__ __forceinline__ float2 csub(float2 a, float2 b) { return make_float2(a.x - b.x, a.y - b.y); }
__device__ __forceinline__ float2 cmuli(float2 a) { return make_float2(-a.y, a.x); }

// ============================================================================
// Kernel A: Cauchy sums (round-4 proven structure). grid (HH, 4), block 128.
// ============================================================================
__global__ __launch_bounds__(128) void s4_cauchy(
    const float* __restrict__ A_real,
    const float* __restrict__ A_imag,
    const float* __restrict__ Bm,
    const float* __restrict__ Cm,
    const float* __restrict__ Pm,
    const float* __restrict__ inv_dt)
{
    __shared__ ulonglong2 s_coef[NN / 2][9];

    const int h   = blockIdx.x;
    const int tid = threadIdx.x;

    if (blockIdx.y == 0 && blockIdx.x < 9) {
        const int j = blockIdx.x * 128 + tid;
        if (j <= 1024) {
            float s, c;
            sincosf((float)j * (3.14159265358979323846f / 2048.0f), &s, &c);
            g_tw[j] = make_float2(c, s);
        }
    }

    if (tid < NN) {
        const int n  = tid;
        const float dt = expf(inv_dt[h]);
        const float ar = -expf(A_real[h * NN + n]) * dt;
        const float ai =  A_imag[h * NN + n] * dt;

        const int base = (h * NN + n) * 2;
        const float bx = Bm[base], by = Bm[base + 1];
        const float cx = Cm[base], cy = Cm[base + 1];
        const float px = Pm[base], py = Pm[base + 1];

        float vr[4], vi[4];
        vr[0] = (bx * cx - by * cy) * dt;  vi[0] = (bx * cy + by * cx) * dt;
        vr[1] = (bx * px + by * py) * dt;  vi[1] = (by * px - bx * py) * dt;
        vr[2] = (px * cx - py * cy) * dt;  vi[2] = (px * cy + py * cx) * dt;
        vr[3] = (px * px + py * py) * dt;  vi[3] = 0.0f;

        float* c = (float*)&s_coef[n >> 1][0];
        const int o = n & 1;
        const float ccoef = -2.0f * ar;
        c[0 + o] = ar * ar + ai * ai;              // m
        c[2 + o] = ccoef * ccoef;                  // c^2
        #pragma unroll
        for (int ab = 0; ab < 4; ab++) {
            const float p = -2.0f * (vr[ab] * ar + vi[ab] * ai);
            const float q =  2.0f * vr[ab];
            const int bo = 4 + ab * 8;
            c[bo + 0 + o] = p;
            c[bo + 2 + o] = q * ccoef;             // qc
            c[bo + 4 + o] = q;
            c[bo + 6 + o] = -p * ccoef;            // npc
        }
    }
    __syncthreads();

    const float ANG = 3.14159265358979323846f / 4096.0f;
    const int base_l = blockIdx.y * 512 + tid;

    float yv[4];
    ull y2v[4], ny2v[4];
    #pragma unroll
    for (int b = 0; b < 4; b++) {
        const float y = 2.0f * tanf((float)(base_l + b * 128) * ANG);
        yv[b] = y;
        y2v[b]  = f2_pack(y * y, y * y);
        ny2v[b] = y2v[b] ^ 0x8000000080000000ULL;
    }

    ull accr[4][4], acci[4][4];
    #pragma unroll
    for (int b = 0; b < 4; b++)
        #pragma unroll
        for (int ab = 0; ab < 4; ab++) { accr[b][ab] = 0; acci[b][ab] = 0; }

    #pragma unroll 4
    for (int k = 0; k < NN / 2; k++) {
        const ulonglong2* cc = &s_coef[k][0];
        const ulonglong2 c0 = cc[0];

        ull dinv[4], y2inv[4], invv[4];
        #pragma unroll
        for (int b = 0; b < 4; b++) {
            const ull dr  = f2_add(c0.x, ny2v[b]);
            const ull mag = f2_fma(dr, dr, f2_mul(c0.y, y2v[b]));
            const float2 m = f2_unpack(mag);
            const ull inv = f2_pack(frcp(m.x), frcp(m.y));
            invv[b]  = inv;
            dinv[b]  = f2_mul(dr, inv);
            y2inv[b] = f2_mul(y2v[b], inv);
        }

        #pragma unroll
        for (int ab = 0; ab < 4; ab++) {
            const ulonglong2 ca = cc[1 + 2 * ab];
            const ulonglong2 cb = cc[2 + 2 * ab];
            #pragma unroll
            for (int b = 0; b < 4; b++) {
                accr[b][ab] = f2_fma(ca.x, dinv[b], f2_fma(ca.y, y2inv[b], accr[b][ab]));
                acci[b][ab] = f2_fma(cb.x, dinv[b], f2_fma(cb.y, invv[b],  acci[b][ab]));
            }
        }
    }

    #pragma unroll
    for (int b = 0; b < 4; b++) {
        const float y = yv[b];
        const int   l = base_l + b * 128;
        const float2 sr0 = f2_unpack(accr[b][0]), si0 = f2_unpack(acci[b][0]);
        const float2 sr1 = f2_unpack(accr[b][1]), si1 = f2_unpack(acci[b][1]);
        const float2 sr2 = f2_unpack(accr[b][2]), si2 = f2_unpack(acci[b][2]);
        const float2 sr3 = f2_unpack(accr[b][3]), si3 = f2_unpack(acci[b][3]);
        const float r00r = sr0.x + sr0.y, r00i = (si0.x + si0.y) * y;
        const float r01r = sr1.x + sr1.y, r01i = (si1.x + si1.y) * y;
        const float r10r = sr2.x + sr2.y, r10i = (si2.x + si2.y) * y;
        const float r11r = sr3.x + sr3.y, r11i = (si3.x + si3.y) * y;

        const float cr = 1.0f + r11r, ci = r11i;
        const float cinv = frcp(cr * cr + ci * ci);
        const float trm = r01r * r10r - r01i * r10i;
        const float tim = r01r * r10i + r01i * r10r;
        const float qr = (trm * cr + tim * ci) * cinv;
        const float qi = (tim * cr - trm * ci) * cinv;
        const float kr = r00r - qr;
        const float ki = r00i - qi;
        const float hy = 0.5f * y;
        float fr = kr - ki * hy;
        float fi = ki + kr * hy;
        if (l == 0) fi = 0.0f;
        g_X[h * LF + l] = make_float2(fr, fi);
    }

    if (blockIdx.y == 3 && tid == 0) {
        const float y  = 2.0f * tanf(2048.0f * ANG);
        const float y2 = y * y;
        float rr[4] = {0, 0, 0, 0}, riy[4] = {0, 0, 0, 0};
        for (int n = 0; n < NN; n++) {
            const float* c = (const float*)&s_coef[n >> 1][0];
            const int o = n & 1;
            const float dr = c[0 + o] - y2;
            const float inv = frcp(dr * dr + c[2 + o] * y2);
            const float dinv = dr * inv;
            const float y2inv = y2 * inv;
            #pragma unroll
            for (int ab = 0; ab < 4; ab++) {
                const int bo = 4 + ab * 8;
                rr[ab]  += c[bo + 0 + o] * dinv + c[bo + 2 + o] * y2inv;
                riy[ab] += c[bo + 4 + o] * dinv + c[bo + 6 + o] * inv;
            }
        }
        const float r00r = rr[0];
        const float r01r = rr[1], r01i = riy[1] * y;
        const float r10r = rr[2], r10i = riy[2] * y;
        const float r11r = rr[3], r11i = riy[3] * y;
        const float cr = 1.0f + r11r, ci = r11i;
        const float cinv = frcp(cr * cr + ci * ci);
        const float trm = r01r * r10r - r01i * r10i;
        const float tim = r01r * r10i + r01i * r10r;
        const float qr = (trm * cr + tim * ci) * cinv;
        const float qi = (tim * cr - trm * ci) * cinv;
        const float kr = r00r - qr;
        const float ki = riy[0] * y - qi;
        const float fr = kr - ki * (0.5f * y);
        g_X[h * LF + 2048] = make_float2(fr, 0.0f);
    }
}

// ============================================================================
// Kernel B: irfft-4096 via complex iFFT-2048, radix-8 passes, 8 elem/thread.
// FIX vs round 6: stage-(s+2) base twiddle is W_M^(j*2^(9-s)) = tw[j<<(10-s)]
// (table stores W_4096 powers), was erroneously tw[j<<(9-s)].
// ============================================================================
#define IDX(i) ((i) + ((i) >> 3))
#define R2C 0.70710678118654752f

__device__ __forceinline__ void radix8_pass(float2* spec, const float2* tw, int tid, int s) {
    const int hh   = 1 << (s - 1);
    const int j    = tid & (hh - 1);
    const int base = ((tid >> (s - 1)) << (s + 2)) + j;

    float2 x[8];
    #pragma unroll
    for (int q = 0; q < 8; q++) x[q] = spec[IDX(base + q * hh)];

    const float2 w4 = tw[j << (10 - s)];   // W_M^(j*2^(9-s))  [FIXED]
    const float2 w2 = csq(w4);             // stage s+1 twiddle
    const float2 w1 = csq(w2);             // stage s twiddle

    // stage s: pairs (q, q+1), all twiddle w1
    float2 a[8];
    #pragma unroll
    for (int p = 0; p < 4; p++) {
        const float2 t = cmul(w1, x[2 * p + 1]);
        a[2 * p]     = cadd(x[2 * p], t);
        a[2 * p + 1] = csub(x[2 * p], t);
    }
    // stage s+1: pairs (o,o+2) tw=w2, (o+1,o+3) tw=i*w2
    float2 b[8];
    #pragma unroll
    for (int g = 0; g < 2; g++) {
        const int o = 4 * g;
        const float2 t2 = cmul(w2, a[o + 2]);
        const float2 t3 = cmuli(cmul(w2, a[o + 3]));
        b[o + 0] = cadd(a[o + 0], t2);
        b[o + 2] = csub(a[o + 0], t2);
        b[o + 1] = cadd(a[o + 1], t3);
        b[o + 3] = csub(a[o + 1], t3);
    }
    // stage s+2: pairs (q, q+4), twiddles w4, w4*u, i*w4, i*u*w4 (u=e^{i pi/4})
    const float2 u  = make_float2(R2C, R2C);
    const float2 vu = cmul(w4, u);
    const float2 t4 = cmul(w4, b[4]);
    const float2 t5 = cmul(vu, b[5]);
    const float2 t6 = cmul(cmuli(w4), b[6]);
    const float2 t7 = cmul(cmuli(vu), b[7]);

    spec[IDX(base + 0 * hh)] = cadd(b[0], t4);
    spec[IDX(base + 4 * hh)] = csub(b[0], t4);
    spec[IDX(base + 1 * hh)] = cadd(b[1], t5);
    spec[IDX(base + 5 * hh)] = csub(b[1], t5);
    spec[IDX(base + 2 * hh)] = cadd(b[2], t6);
    spec[IDX(base + 6 * hh)] = csub(b[2], t6);
    spec[IDX(base + 3 * hh)] = cadd(b[3], t7);
    spec[IDX(base + 7 * hh)] = csub(b[3], t7);
}

__global__ __launch_bounds__(256) void s4_fft(float* __restrict__ out)
{
    __shared__ float2 Xs[2305];
    __shared__ float2 spec[2304];
    __shared__ float2 tw[1025];

    const int h   = blockIdx.x;
    const int tid = threadIdx.x;

    const float2* Xh = &g_X[h * LF];
    #pragma unroll
    for (int m = 0; m < 8; m++) {
        const int i = tid + m * 256;
        Xs[IDX(i)] = Xh[i];
    }
    if (tid == 0) Xs[IDX(2048)] = Xh[2048];
    for (int j = tid; j <= 1024; j += 256) tw[j] = g_tw[j];
    __syncthreads();

    // build Z at bit-reversed positions + in-register radix-8 (stages 1-3, twiddle-free)
    {
        const int rv = __brev(tid) >> 24;             // rev8(tid)
        float2 c[8];
        #pragma unroll
        for (int q = 0; q < 8; q++) {
            const int rq = (q == 0) ? 0 : (q == 1) ? 4 : (q == 2) ? 2 : (q == 3) ? 6
                         : (q == 4) ? 1 : (q == 5) ? 5 : (q == 6) ? 3 : 7;   // rev3(q)
            const int k  = rq * 256 + rv;
            const float2 Xk = Xs[IDX(k)];
            const float2 Xm = Xs[IDX(2048 - k)];
            float2 w;
            if (k <= 1024) w = tw[k];
            else { const float2 t = tw[k - 1024]; w = make_float2(-t.y, t.x); }
            const float arr = Xk.x + Xm.x, aii = Xk.y - Xm.y;
            const float brr = Xk.x - Xm.x, bii = Xk.y + Xm.y;
            c[q] = make_float2(arr - (w.x * bii + w.y * brr),
                               aii + (w.x * brr - w.y * bii));
        }
        float2 a[8];
        #pragma unroll
        for (int p = 0; p < 4; p++) {
            a[2 * p]     = cadd(c[2 * p], c[2 * p + 1]);
            a[2 * p + 1] = csub(c[2 * p], c[2 * p + 1]);
        }
        float2 b[8];
        #pragma unroll
        for (int g = 0; g < 2; g++) {
            const int o = 4 * g;
            const float2 t3 = cmuli(a[o + 3]);
            b[o + 0] = cadd(a[o + 0], a[o + 2]);
            b[o + 2] = csub(a[o + 0], a[o + 2]);
            b[o + 1] = cadd(a[o + 1], t3);
            b[o + 3] = csub(a[o + 1], t3);
        }
        const float2 t4 = b[4];
        const float2 t5 = make_float2(R2C * (b[5].x - b[5].y), R2C * (b[5].x + b[5].y));
        const float2 t6 = cmuli(b[6]);
        const float2 t7 = make_float2(-R2C * (b[7].x + b[7].y), R2C * (b[7].x - b[7].y));
        const int p0 = 8 * tid;
        spec[IDX(p0 + 0)] = cadd(b[0], t4);
        spec[IDX(p0 + 4)] = csub(b[0], t4);
        spec[IDX(p0 + 1)] = cadd(b[1], t5);
        spec[IDX(p0 + 5)] = csub(b[1], t5);
        spec[IDX(p0 + 2)] = cadd(b[2], t6);
        spec[IDX(p0 + 6)] = csub(b[2], t6);
        spec[IDX(p0 + 3)] = cadd(b[3], t7);
        spec[IDX(p0 + 7)] = csub(b[3], t7);
    }
    __syncthreads();

    radix8_pass(spec, tw, tid, 4);    // stages 4,5,6
    __syncthreads();
    radix8_pass(spec, tw, tid, 7);    // stages 7,8,9
    __syncthreads();

    // stages 10,11: fused radix-4, 512 butterflies, 2 per thread
    #pragma unroll
    for (int m = 0; m < 2; m++) {
        const int j = tid + m * 256;
        const float2 w2 = tw[2 * j];          // W_M^j
        const float2 w1 = csq(w2);            // W_M^(2j), stage-10 twiddle
        const float2 x0 = spec[IDX(j)];
        const float2 x1 = spec[IDX(j + 512)];
        const float2 x2 = spec[IDX(j + 1024)];
        const float2 x3 = spec[IDX(j + 1536)];
        const float2 t1 = cmul(w1, x1);
        const float2 a0 = cadd(x0, t1), a1 = csub(x0, t1);
        const float2 t3 = cmul(w1, x3);
        const float2 a2 = cadd(x2, t3), a3 = csub(x2, t3);
        const float2 t2 = cmul(w2, a2);
        const float2 c3 = cmuli(cmul(w2, a3));
        spec[IDX(j)]        = cadd(a0, t2);
        spec[IDX(j + 1024)] = csub(a0, t2);
        spec[IDX(j + 512)]  = cadd(a1, c3);
        spec[IDX(j + 1536)] = csub(a1, c3);
    }
    __syncthreads();

    float2* out2 = (float2*)(out + h * LL);
    const float scale = 1.0f / (float)LL;
    #pragma unroll
    for (int m = 0; m < 8; m++) {
        const int n = tid + m * 256;
        const float2 z = spec[IDX(n)];
        out2[n] = make_float2(z.x * scale, z.y * scale);
    }
}

extern "C" void kernel_launch(void* const* d_in, const int* in_sizes, int n_in,
                              void* d_out, int out_size)
{
    (void)in_sizes; (void)n_in; (void)out_size;
    dim3 gridA(HH, 4);
    s4_cauchy<<<gridA, 128>>>(
        (const float*)d_in[0],   // A_real (H, N)
        (const float*)d_in[1],   // A_imag (H, N)
        (const float*)d_in[2],   // B (1, H, N, 2)
        (const float*)d_in[3],   // C (1, H, N, 2)
        (const float*)d_in[4],   // P (1, H, N, 2)
        (const float*)d_in[5]);  // inv_dt (H,)
    s4_fft<<<HH, 256>>>((float*)d_out);
}

// round 8
// speedup vs baseline: 1.1377x; 1.0130x over previous
#include <cuda_runtime.h>
#include <math.h>

#define HH 512
#define NN 64
#define LL 4096
#define MM 2048
#define LF 2049

typedef unsigned long long ull;

__device__ float2 g_X[HH * LF];   // Cauchy spectrum X[h][l], l=0..2048
__device__ float2 g_tw[1025];     // exp(+i*pi*j/2048), j=0..1024

__device__ __forceinline__ ull f2_fma(ull a, ull b, ull c) {
    ull d; asm("fma.rn.f32x2 %0, %1, %2, %3;" : "=l"(d) : "l"(a), "l"(b), "l"(c)); return d;
}
__device__ __forceinline__ ull f2_mul(ull a, ull b) {
    ull d; asm("mul.rn.f32x2 %0, %1, %2;" : "=l"(d) : "l"(a), "l"(b)); return d;
}
__device__ __forceinline__ ull f2_add(ull a, ull b) {
    ull d; asm("add.rn.f32x2 %0, %1, %2;" : "=l"(d) : "l"(a), "l"(b)); return d;
}
__device__ __forceinline__ ull f2_pack(float lo, float hi) {
    ull d; asm("mov.b64 %0, {%1, %2};" : "=l"(d) : "f"(lo), "f"(hi)); return d;
}
__device__ __forceinline__ float2 f2_unpack(ull a) {
    float lo, hi; asm("mov.b64 {%0, %1}, %2;" : "=f"(lo), "=f"(hi) : "l"(a));
    return make_float2(lo, hi);
}
__device__ __forceinline__ float frcp(float x) {
    float r; asm("rcp.approx.f32 %0, %1;" : "=f"(r) : "f"(x)); return r;
}

// complex helpers
__device__ __forceinline__ float2 cmul(float2 a, float2 b) {
    return make_float2(a.x * b.x - a.y * b.y, a.x * b.y + a.y * b.x);
}
__device__ __forceinline__ float2 csq(float2 a) {
    return make_float2(a.x * a.x - a.y * a.y, 2.0f * a.x * a.y);
}
__device__ __forceinline__ float2 cadd(float2 a, float2 b) { return make_float2(a.x + b.x, a.y + b.y); }
__device__ __forceinline__ float2 csub(float2 a, float2 b) { return make_float2(a.x - b.x, a.y - b.y); }
__device__ __forceinline__ float2 cmuli(float2 a) { return make_float2(-a.y, a.x); }

// ============================================================================
// Kernel A: Cauchy sums. grid (HH, 4), block 128. 4 bins/thread.
// ============================================================================
__global__ __launch_bounds__(128) void s4_cauchy(
    const float* __restrict__ A_real,
    const float* __restrict__ A_imag,
    const float* __restrict__ Bm,
    const float* __restrict__ Cm,
    const float* __restrict__ Pm,
    const float* __restrict__ inv_dt)
{
    __shared__ ulonglong2 s_coef[NN / 2][9];

    const int h   = blockIdx.x;
    const int tid = threadIdx.x;

    if (blockIdx.y == 0 && blockIdx.x < 9) {
        const int j = blockIdx.x * 128 + tid;
        if (j <= 1024) {
            float s, c;
            sincosf((float)j * (3.14159265358979323846f / 2048.0f), &s, &c);
            g_tw[j] = make_float2(c, s);
        }
    }

    if (tid < NN) {
        const int n  = tid;
        const float dt = expf(inv_dt[h]);
        const float ar = -expf(A_real[h * NN + n]) * dt;
        const float ai =  A_imag[h * NN + n] * dt;

        const int base = (h * NN + n) * 2;
        const float bx = Bm[base], by = Bm[base + 1];
        const float cx = Cm[base], cy = Cm[base + 1];
        const float px = Pm[base], py = Pm[base + 1];

        float vr[4], vi[4];
        vr[0] = (bx * cx - by * cy) * dt;  vi[0] = (bx * cy + by * cx) * dt;
        vr[1] = (bx * px + by * py) * dt;  vi[1] = (by * px - bx * py) * dt;
        vr[2] = (px * cx - py * cy) * dt;  vi[2] = (px * cy + py * cx) * dt;
        vr[3] = (px * px + py * py) * dt;  vi[3] = 0.0f;

        float* c = (float*)&s_coef[n >> 1][0];
        const int o = n & 1;
        const float ccoef = -2.0f * ar;
        c[0 + o] = ar * ar + ai * ai;              // m
        c[2 + o] = ccoef * ccoef;                  // c^2
        #pragma unroll
        for (int ab = 0; ab < 4; ab++) {
            const float p = -2.0f * (vr[ab] * ar + vi[ab] * ai);
            const float q =  2.0f * vr[ab];
            const int bo = 4 + ab * 8;
            c[bo + 0 + o] = p;
            c[bo + 2 + o] = q * ccoef;             // qc
            c[bo + 4 + o] = q;
            c[bo + 6 + o] = -p * ccoef;            // npc
        }
    }
    __syncthreads();

    const float ANG = 3.14159265358979323846f / 4096.0f;
    const int base_l = blockIdx.y * 512 + tid;

    float yv[4];
    ull y2v[4], ny2v[4];
    #pragma unroll
    for (int b = 0; b < 4; b++) {
        const float ang = (float)(base_l + b * 128) * ANG;
        float s_, c_;
        __sincosf(ang, &s_, &c_);
        const float y = 2.0f * s_ * frcp(c_);      // fast tan (MUFU path)
        yv[b] = y;
        y2v[b]  = f2_pack(y * y, y * y);
        ny2v[b] = y2v[b] ^ 0x8000000080000000ULL;
    }

    ull accr[4][4], acci[4][4];
    #pragma unroll
    for (int b = 0; b < 4; b++)
        #pragma unroll
        for (int ab = 0; ab < 4; ab++) { accr[b][ab] = 0; acci[b][ab] = 0; }

    #pragma unroll 4
    for (int k = 0; k < NN / 2; k++) {
        const ulonglong2* cc = &s_coef[k][0];
        const ulonglong2 c0 = cc[0];

        ull dinv[4], y2inv[4], invv[4];
        #pragma unroll
        for (int b = 0; b < 4; b++) {
            const ull dr  = f2_add(c0.x, ny2v[b]);
            const ull mag = f2_fma(dr, dr, f2_mul(c0.y, y2v[b]));
            const float2 m = f2_unpack(mag);
            const ull inv = f2_pack(frcp(m.x), frcp(m.y));
            invv[b]  = inv;
            dinv[b]  = f2_mul(dr, inv);
            y2inv[b] = f2_mul(y2v[b], inv);
        }

        #pragma unroll
        for (int ab = 0; ab < 4; ab++) {
            const ulonglong2 ca = cc[1 + 2 * ab];
            const ulonglong2 cb = cc[2 + 2 * ab];
            #pragma unroll
            for (int b = 0; b < 4; b++) {
                accr[b][ab] = f2_fma(ca.x, dinv[b], f2_fma(ca.y, y2inv[b], accr[b][ab]));
                acci[b][ab] = f2_fma(cb.x, dinv[b], f2_fma(cb.y, invv[b],  acci[b][ab]));
            }
        }
    }

    #pragma unroll
    for (int b = 0; b < 4; b++) {
        const float y = yv[b];
        const int   l = base_l + b * 128;
        const float2 sr0 = f2_unpack(accr[b][0]), si0 = f2_unpack(acci[b][0]);
        const float2 sr1 = f2_unpack(accr[b][1]), si1 = f2_unpack(acci[b][1]);
        const float2 sr2 = f2_unpack(accr[b][2]), si2 = f2_unpack(acci[b][2]);
        const float2 sr3 = f2_unpack(accr[b][3]), si3 = f2_unpack(acci[b][3]);
        const float r00r = sr0.x + sr0.y, r00i = (si0.x + si0.y) * y;
        const float r01r = sr1.x + sr1.y, r01i = (si1.x + si1.y) * y;
        const float r10r = sr2.x + sr2.y, r10i = (si2.x + si2.y) * y;
        const float r11r = sr3.x + sr3.y, r11i = (si3.x + si3.y) * y;

        const float cr = 1.0f + r11r, ci = r11i;
        const float cinv = frcp(cr * cr + ci * ci);
        const float trm = r01r * r10r - r01i * r10i;
        const float tim = r01r * r10i + r01i * r10r;
        const float qr = (trm * cr + tim * ci) * cinv;
        const float qi = (tim * cr - trm * ci) * cinv;
        const float kr = r00r - qr;
        const float ki = r00i - qi;
        const float hy = 0.5f * y;
        float fr = kr - ki * hy;
        float fi = ki + kr * hy;
        if (l == 0) fi = 0.0f;
        g_X[h * LF + l] = make_float2(fr, fi);
    }

    if (blockIdx.y == 3 && tid == 0) {
        const float y  = 2.0f * tanf(2048.0f * ANG);
        const float y2 = y * y;
        float rr[4] = {0, 0, 0, 0}, riy[4] = {0, 0, 0, 0};
        for (int n = 0; n < NN; n++) {
            const float* c = (const float*)&s_coef[n >> 1][0];
            const int o = n & 1;
            const float dr = c[0 + o] - y2;
            const float inv = frcp(dr * dr + c[2 + o] * y2);
            const float dinv = dr * inv;
            const float y2inv = y2 * inv;
            #pragma unroll
            for (int ab = 0; ab < 4; ab++) {
                const int bo = 4 + ab * 8;
                rr[ab]  += c[bo + 0 + o] * dinv + c[bo + 2 + o] * y2inv;
                riy[ab] += c[bo + 4 + o] * dinv + c[bo + 6 + o] * inv;
            }
        }
        const float r00r = rr[0];
        const float r01r = rr[1], r01i = riy[1] * y;
        const float r10r = rr[2], r10i = riy[2] * y;
        const float r11r = rr[3], r11i = riy[3] * y;
        const float cr = 1.0f + r11r, ci = r11i;
        const float cinv = frcp(cr * cr + ci * ci);
        const float trm = r01r * r10r - r01i * r10i;
        const float tim = r01r * r10i + r01i * r10r;
        const float qr = (trm * cr + tim * ci) * cinv;
        const float qi = (tim * cr - trm * ci) * cinv;
        const float kr = r00r - qr;
        const float ki = riy[0] * y - qi;
        const float fr = kr - ki * (0.5f * y);
        g_X[h * LF + 2048] = make_float2(fr, 0.0f);
    }
}

// ============================================================================
// Kernel B: irfft-4096 via complex iFFT-2048, radix-8, 8 elem/thread.
// Single aliased smem buffer for X staging AND FFT workspace (26.6 KB total).
// ============================================================================
#define IDX(i) ((i) + ((i) >> 3))
#define R2C 0.70710678118654752f

__device__ __forceinline__ void radix8_pass(float2* spec, const float2* tw, int tid, int s) {
    const int hh   = 1 << (s - 1);
    const int j    = tid & (hh - 1);
    const int base = ((tid >> (s - 1)) << (s + 2)) + j;

    float2 x[8];
    #pragma unroll
    for (int q = 0; q < 8; q++) x[q] = spec[IDX(base + q * hh)];

    const float2 w4 = tw[j << (10 - s)];   // W_M^(j*2^(9-s))
    const float2 w2 = csq(w4);
    const float2 w1 = csq(w2);

    float2 a[8];
    #pragma unroll
    for (int p = 0; p < 4; p++) {
        const float2 t = cmul(w1, x[2 * p + 1]);
        a[2 * p]     = cadd(x[2 * p], t);
        a[2 * p + 1] = csub(x[2 * p], t);
    }
    float2 b[8];
    #pragma unroll
    for (int g = 0; g < 2; g++) {
        const int o = 4 * g;
        const float2 t2 = cmul(w2, a[o + 2]);
        const float2 t3 = cmuli(cmul(w2, a[o + 3]));
        b[o + 0] = cadd(a[o + 0], t2);
        b[o + 2] = csub(a[o + 0], t2);
        b[o + 1] = cadd(a[o + 1], t3);
        b[o + 3] = csub(a[o + 1], t3);
    }
    const float2 u  = make_float2(R2C, R2C);
    const float2 vu = cmul(w4, u);
    const float2 t4 = cmul(w4, b[4]);
    const float2 t5 = cmul(vu, b[5]);
    const float2 t6 = cmul(cmuli(w4), b[6]);
    const float2 t7 = cmul(cmuli(vu), b[7]);

    spec[IDX(base + 0 * hh)] = cadd(b[0], t4);
    spec[IDX(base + 4 * hh)] = csub(b[0], t4);
    spec[IDX(base + 1 * hh)] = cadd(b[1], t5);
    spec[IDX(base + 5 * hh)] = csub(b[1], t5);
    spec[IDX(base + 2 * hh)] = cadd(b[2], t6);
    spec[IDX(base + 6 * hh)] = csub(b[2], t6);
    spec[IDX(base + 3 * hh)] = cadd(b[3], t7);
    spec[IDX(base + 7 * hh)] = csub(b[3], t7);
}

__global__ __launch_bounds__(256) void s4_fft(float* __restrict__ out)
{
    __shared__ float2 buf[2305];    // X staging, then FFT workspace (aliased)
    __shared__ float2 tw[1025];

    const int h   = blockIdx.x;
    const int tid = threadIdx.x;

    // phase 0: coalesced X load into buf
    const float2* Xh = &g_X[h * LF];
    #pragma unroll
    for (int m = 0; m < 8; m++) {
        const int i = tid + m * 256;
        buf[IDX(i)] = Xh[i];
    }
    if (tid == 0) buf[IDX(2048)] = Xh[2048];
    for (int j = tid; j <= 1024; j += 256) tw[j] = g_tw[j];
    __syncthreads();

    // phase 1: gather X (bit-reversed), build Z, in-register radix-8 (stages 1-3)
    {
        const int rv = __brev(tid) >> 24;             // rev8(tid)
        float2 c[8];
        #pragma unroll
        for (int q = 0; q < 8; q++) {
            const int rq = (q == 0) ? 0 : (q == 1) ? 4 : (q == 2) ? 2 : (q == 3) ? 6
                         : (q == 4) ? 1 : (q == 5) ? 5 : (q == 6) ? 3 : 7;   // rev3(q)
            const int k  = rq * 256 + rv;
            const float2 Xk = buf[IDX(k)];
            const float2 Xm = buf[IDX(2048 - k)];
            float2 w;
            if (k <= 1024) w = tw[k];
            else { const float2 t = tw[k - 1024]; w = make_float2(-t.y, t.x); }
            const float arr = Xk.x + Xm.x, aii = Xk.y - Xm.y;
            const float brr = Xk.x - Xm.x, bii = Xk.y + Xm.y;
            c[q] = make_float2(arr - (w.x * bii + w.y * brr),
                               aii + (w.x * brr - w.y * bii));
        }
        float2 a[8];
        #pragma unroll
        for (int p = 0; p < 4; p++) {
            a[2 * p]     = cadd(c[2 * p], c[2 * p + 1]);
            a[2 * p + 1] = csub(c[2 * p], c[2 * p + 1]);
        }
        float2 b[8];
        #pragma unroll
        for (int g = 0; g < 2; g++) {
            const int o = 4 * g;
            const float2 t3 = cmuli(a[o + 3]);
            b[o + 0] = cadd(a[o + 0], a[o + 2]);
            b[o + 2] = csub(a[o + 0], a[o + 2]);
            b[o + 1] = cadd(a[o + 1], t3);
            b[o + 3] = csub(a[o + 1], t3);
        }
        const float2 t4 = b[4];
        const float2 t5 = make_float2(R2C * (b[5].x - b[5].y), R2C * (b[5].x + b[5].y));
        const float2 t6 = cmuli(b[6]);
        const float2 t7 = make_float2(-R2C * (b[7].x + b[7].y), R2C * (b[7].x - b[7].y));

        __syncthreads();    // everyone done READING buf before overwriting it

        const int p0 = 8 * tid;
        buf[IDX(p0 + 0)] = cadd(b[0], t4);
        buf[IDX(p0 + 4)] = csub(b[0], t4);
        buf[IDX(p0 + 1)] = cadd(b[1], t5);
        buf[IDX(p0 + 5)] = csub(b[1], t5);
        buf[IDX(p0 + 2)] = cadd(b[2], t6);
        buf[IDX(p0 + 6)] = csub(b[2], t6);
        buf[IDX(p0 + 3)] = cadd(b[3], t7);
        buf[IDX(p0 + 7)] = csub(b[3], t7);
    }
    __syncthreads();

    radix8_pass(buf, tw, tid, 4);    // stages 4,5,6
    __syncthreads();
    radix8_pass(buf, tw, tid, 7);    // stages 7,8,9
    __syncthreads();

    // stages 10,11: fused radix-4, 512 butterflies, 2 per thread
    #pragma unroll
    for (int m = 0; m < 2; m++) {
        const int j = tid + m * 256;
        const float2 w2 = tw[2 * j];          // W_M^j
        const float2 w1 = csq(w2);
        const float2 x0 = buf[IDX(j)];
        const float2 x1 = buf[IDX(j + 512)];
        const float2 x2 = buf[IDX(j + 1024)];
        const float2 x3 = buf[IDX(j + 1536)];
        const float2 t1 = cmul(w1, x1);
        const float2 a0 = cadd(x0, t1), a1 = csub(x0, t1);
        const float2 t3 = cmul(w1, x3);
        const float2 a2 = cadd(x2, t3), a3 = csub(x2, t3);
        const float2 t2 = cmul(w2, a2);
        const float2 c3 = cmuli(cmul(w2, a3));
        buf[IDX(j)]        = cadd(a0, t2);
        buf[IDX(j + 1024)] = csub(a0, t2);
        buf[IDX(j + 512)]  = cadd(a1, c3);
        buf[IDX(j + 1536)] = csub(a1, c3);
    }
    __syncthreads();

    float2* out2 = (float2*)(out + h * LL);
    const float scale = 1.0f / (float)LL;
    #pragma unroll
    for (int m = 0; m < 8; m++) {
        const int n = tid + m * 256;
        const float2 z = buf[IDX(n)];
        out2[n] = make_float2(z.x * scale, z.y * scale);
    }
}

extern "C" void kernel_launch(void* const* d_in, const int* in_sizes, int n_in,
                              void* d_out, int out_size)
{
    (void)in_sizes; (void)n_in; (void)out_size;
    dim3 gridA(HH, 4);
    s4_cauchy<<<gridA, 128>>>(
        (const float*)d_in[0],   // A_real (H, N)
        (const float*)d_in[1],   // A_imag (H, N)
        (const float*)d_in[2],   // B (1, H, N, 2)
        (const float*)d_in[3],   // C (1, H, N, 2)
        (const float*)d_in[4],   // P (1, H, N, 2)
        (const float*)d_in[5]);  // inv_dt (H,)
    s4_fft<<<HH, 256>>>((float*)d_out);
}